// round 2
// baseline (speedup 1.0000x reference)
#include <cuda_runtime.h>

// Problem: B=256, N=1024, D=512, K=2.
// out[row][k] = softmax_k( exp(logit_scale) * dot(x[row], tf[k]/||tf[k]||) )
// rows = B*N = 262144.

#define D 512
#define KP 2
#define ROWS (256 * 1024)

// Normalized + scaled prompt weights (K=2 rows of D=512 floats).
__device__ float g_w[KP][D];

// ---- prep: normalize text_features, fold in exp(logit_scale) ----
__global__ void prep_kernel(const float* __restrict__ tf,
                            const float* __restrict__ logit_scale) {
    int t = threadIdx.x;          // 0..511
    float a0 = tf[t];
    float a1 = tf[D + t];
    float s0 = a0 * a0;
    float s1 = a1 * a1;
    #pragma unroll
    for (int o = 16; o; o >>= 1) {
        s0 += __shfl_xor_sync(0xffffffffu, s0, o);
        s1 += __shfl_xor_sync(0xffffffffu, s1, o);
    }
    __shared__ float sm0[16], sm1[16];
    int w = t >> 5, l = t & 31;
    if (l == 0) { sm0[w] = s0; sm1[w] = s1; }
    __syncthreads();
    __shared__ float inv0, inv1, scl;
    if (t == 0) {
        float t0 = 0.f, t1 = 0.f;
        #pragma unroll
        for (int i = 0; i < 16; i++) { t0 += sm0[i]; t1 += sm1[i]; }
        inv0 = rsqrtf(t0);
        inv1 = rsqrtf(t1);
        scl  = __expf(logit_scale[0]);
    }
    __syncthreads();
    g_w[0][t] = a0 * inv0 * scl;
    g_w[1][t] = a1 * inv1 * scl;
}

// ---- main: one warp per row, persistent grid-stride ----
__global__ __launch_bounds__(256, 4)
void prompts_kernel(const float4* __restrict__ x, float2* __restrict__ out) {
    const int lane  = threadIdx.x & 31;
    const int warp  = (blockIdx.x * blockDim.x + threadIdx.x) >> 5;
    const int nwarp = (gridDim.x * blockDim.x) >> 5;

    // Load weights into registers once per warp (lane covers 4 passes of 32 float4).
    float4 w0[4], w1[4];
    const float4* gw0 = reinterpret_cast<const float4*>(g_w[0]);
    const float4* gw1 = reinterpret_cast<const float4*>(g_w[1]);
    #pragma unroll
    for (int p = 0; p < 4; p++) {
        w0[p] = gw0[p * 32 + lane];
        w1[p] = gw1[p * 32 + lane];
    }

    for (int r = warp; r < ROWS; r += nwarp) {
        const float4* xr = x + (size_t)r * (D / 4);
        float s0 = 0.f, s1 = 0.f;
        #pragma unroll
        for (int p = 0; p < 4; p++) {
            float4 v = __ldg(xr + p * 32 + lane);
            s0 = fmaf(v.x, w0[p].x, s0);
            s0 = fmaf(v.y, w0[p].y, s0);
            s0 = fmaf(v.z, w0[p].z, s0);
            s0 = fmaf(v.w, w0[p].w, s0);
            s1 = fmaf(v.x, w1[p].x, s1);
            s1 = fmaf(v.y, w1[p].y, s1);
            s1 = fmaf(v.z, w1[p].z, s1);
            s1 = fmaf(v.w, w1[p].w, s1);
        }
        #pragma unroll
        for (int o = 16; o; o >>= 1) {
            s0 += __shfl_xor_sync(0xffffffffu, s0, o);
            s1 += __shfl_xor_sync(0xffffffffu, s1, o);
        }
        if (lane == 0) {
            float m  = fmaxf(s0, s1);
            float e0 = __expf(s0 - m);
            float e1 = __expf(s1 - m);
            float inv = 1.f / (e0 + e1);
            out[r] = make_float2(e0 * inv, e1 * inv);
        }
    }
}

extern "C" void kernel_launch(void* const* d_in, const int* in_sizes, int n_in,
                              void* d_out, int out_size) {
    const float* x  = (const float*)d_in[0];            // [256,1024,512] f32
    const float* tf = (const float*)d_in[1];            // [2,512] f32
    const float* ls = (const float*)d_in[2];            // [1] f32
    float2* out = (float2*)d_out;                       // [262144,2] f32

    prep_kernel<<<1, 512>>>(tf, ls);
    prompts_kernel<<<2048, 256>>>((const float4*)x, out);
}

// round 4
// speedup vs baseline: 1.0022x; 1.0022x over previous
#include <cuda_runtime.h>

// Problem: B=256, N=1024, D=512, K=2.
// out[row][k] = softmax_k( exp(logit_scale) * dot(x[row], tf[k]/||tf[k]||) )
// rows = B*N = 262144. Single fused kernel, warp-per-row, software-pipelined.

#define D 512
#define ROWS (256 * 1024)
#define GRID 2048
#define TPB 256
#define NWARP ((GRID * TPB) / 32)   // 16384 -> exactly 16 rows per warp

__global__ __launch_bounds__(TPB, 3)
void prompts_kernel(const float4* __restrict__ x,
                    const float4* __restrict__ tf,   // [2*512] floats as float4
                    const float*  __restrict__ ls,
                    float2* __restrict__ out) {
    const int lane = threadIdx.x & 31;
    const int warp = (blockIdx.x * TPB + threadIdx.x) >> 5;
    const unsigned FULL = 0xffffffffu;

    // ---- per-warp weight setup: load tf, normalize, fold exp(logit_scale) ----
    float4 w0[4], w1[4];
    float n0 = 0.f, n1 = 0.f;
    #pragma unroll
    for (int p = 0; p < 4; p++) {
        w0[p] = tf[p * 32 + lane];           // prompt 0: floats [0,512)
        w1[p] = tf[128 + p * 32 + lane];     // prompt 1: floats [512,1024)
        n0 += w0[p].x * w0[p].x + w0[p].y * w0[p].y + w0[p].z * w0[p].z + w0[p].w * w0[p].w;
        n1 += w1[p].x * w1[p].x + w1[p].y * w1[p].y + w1[p].z * w1[p].z + w1[p].w * w1[p].w;
    }
    #pragma unroll
    for (int o = 16; o; o >>= 1) {
        n0 += __shfl_xor_sync(FULL, n0, o);
        n1 += __shfl_xor_sync(FULL, n1, o);
    }
    const float scale = __expf(ls[0]);
    const float c0 = rsqrtf(n0) * scale;
    const float c1 = rsqrtf(n1) * scale;
    #pragma unroll
    for (int p = 0; p < 4; p++) {
        w0[p].x *= c0; w0[p].y *= c0; w0[p].z *= c0; w0[p].w *= c0;
        w1[p].x *= c1; w1[p].y *= c1; w1[p].z *= c1; w1[p].w *= c1;
    }

    // ---- main loop: 16 rows/warp, prefetch next row before reducing current ----
    const float4* xr = x + (size_t)warp * (D / 4) + lane;
    float4 v[4];
    #pragma unroll
    for (int p = 0; p < 4; p++) v[p] = __ldcs(xr + p * 32);

    for (int r = warp; r < ROWS; r += NWARP) {
        // prefetch next row (uniform branch; skipped only on last iteration)
        float4 nv[4];
        const int rn = r + NWARP;
        const float4* xn = x + (size_t)rn * (D / 4) + lane;
        if (rn < ROWS) {
            #pragma unroll
            for (int p = 0; p < 4; p++) nv[p] = __ldcs(xn + p * 32);
        }

        float s0 = 0.f, s1 = 0.f;
        #pragma unroll
        for (int p = 0; p < 4; p++) {
            s0 = fmaf(v[p].x, w0[p].x, s0);
            s0 = fmaf(v[p].y, w0[p].y, s0);
            s0 = fmaf(v[p].z, w0[p].z, s0);
            s0 = fmaf(v[p].w, w0[p].w, s0);
            s1 = fmaf(v[p].x, w1[p].x, s1);
            s1 = fmaf(v[p].y, w1[p].y, s1);
            s1 = fmaf(v[p].z, w1[p].z, s1);
            s1 = fmaf(v[p].w, w1[p].w, s1);
        }

        // split-warp reduction: lanes 0-15 reduce s0, lanes 16-31 reduce s1 (6 shuffles)
        const bool hi = (lane & 16);
        float other = __shfl_xor_sync(FULL, hi ? s0 : s1, 16);
        float red = (hi ? s1 : s0) + other;
        #pragma unroll
        for (int o = 8; o; o >>= 1) red += __shfl_xor_sync(FULL, red, o);
        float t1 = __shfl_xor_sync(FULL, red, 16);   // lane 0 receives s1 total

        if (lane == 0) {
            float a = red, b = t1;
            float m  = fmaxf(a, b);
            float e0 = __expf(a - m);
            float e1 = __expf(b - m);
            float inv = 1.f / (e0 + e1);
            out[r] = make_float2(e0 * inv, e1 * inv);
        }

        #pragma unroll
        for (int p = 0; p < 4; p++) v[p] = nv[p];
    }
}

extern "C" void kernel_launch(void* const* d_in, const int* in_sizes, int n_in,
                              void* d_out, int out_size) {
    const float* x  = (const float*)d_in[0];   // [256,1024,512] f32
    const float* tf = (const float*)d_in[1];   // [2,512] f32
    const float* ls = (const float*)d_in[2];   // [1] f32
    float2* out = (float2*)d_out;              // [262144,2] f32

    prompts_kernel<<<GRID, TPB>>>((const float4*)x, (const float4*)tf, ls, out);
}

// round 8
// speedup vs baseline: 1.0691x; 1.0668x over previous
#include <cuda_runtime.h>

// B=256, N=1024, D=512, K=2.
// out[row][k] = softmax_k( exp(logit_scale) * dot(x[row], tf[k]/||tf[k]||) )
// rows = 262144. One fused persistent kernel: 592 blocks = 148 SMs x 4 CTAs,
// exactly one wave (no tail quantization). Warp-per-row grid-stride.

#define D 512
#define ROWS (256 * 1024)
#define GRID 592
#define TPB 256
#define NWARP ((GRID * TPB) / 32)   // 4736 warps

__global__ __launch_bounds__(TPB, 4)
void prompts_kernel(const float4* __restrict__ x,
                    const float4* __restrict__ tf,   // [2*512] floats as float4
                    const float*  __restrict__ ls,
                    float2* __restrict__ out) {
    const int lane = threadIdx.x & 31;
    const int warp = (blockIdx.x * TPB + threadIdx.x) >> 5;
    const unsigned FULL = 0xffffffffu;

    // ---- per-warp weight setup: load tf, normalize, fold exp(logit_scale) ----
    float4 w0[4], w1[4];
    float n0 = 0.f, n1 = 0.f;
    #pragma unroll
    for (int p = 0; p < 4; p++) {
        w0[p] = tf[p * 32 + lane];           // prompt 0: floats [0,512)
        w1[p] = tf[128 + p * 32 + lane];     // prompt 1: floats [512,1024)
        n0 += w0[p].x * w0[p].x + w0[p].y * w0[p].y + w0[p].z * w0[p].z + w0[p].w * w0[p].w;
        n1 += w1[p].x * w1[p].x + w1[p].y * w1[p].y + w1[p].z * w1[p].z + w1[p].w * w1[p].w;
    }
    #pragma unroll
    for (int o = 16; o; o >>= 1) {
        n0 += __shfl_xor_sync(FULL, n0, o);
        n1 += __shfl_xor_sync(FULL, n1, o);
    }
    const float scale = __expf(ls[0]);
    const float c0 = rsqrtf(n0) * scale;
    const float c1 = rsqrtf(n1) * scale;
    #pragma unroll
    for (int p = 0; p < 4; p++) {
        w0[p].x *= c0; w0[p].y *= c0; w0[p].z *= c0; w0[p].w *= c0;
        w1[p].x *= c1; w1[p].y *= c1; w1[p].z *= c1; w1[p].w *= c1;
    }

    // ---- main loop: warp-per-row, pointer increment, simple body ----
    const float4* xr = x + (size_t)warp * (D / 4) + lane;
    const size_t step = (size_t)NWARP * (D / 4);

    for (int r = warp; r < ROWS; r += NWARP, xr += step) {
        float s0 = 0.f, s1 = 0.f;
        #pragma unroll
        for (int p = 0; p < 4; p++) {
            float4 v = __ldcs(xr + p * 32);
            s0 = fmaf(v.x, w0[p].x, s0);
            s0 = fmaf(v.y, w0[p].y, s0);
            s0 = fmaf(v.z, w0[p].z, s0);
            s0 = fmaf(v.w, w0[p].w, s0);
            s1 = fmaf(v.x, w1[p].x, s1);
            s1 = fmaf(v.y, w1[p].y, s1);
            s1 = fmaf(v.z, w1[p].z, s1);
            s1 = fmaf(v.w, w1[p].w, s1);
        }
        #pragma unroll
        for (int o = 16; o; o >>= 1) {
            s0 += __shfl_xor_sync(FULL, s0, o);
            s1 += __shfl_xor_sync(FULL, s1, o);
        }
        if (lane == 0) {
            float m  = fmaxf(s0, s1);
            float e0 = __expf(s0 - m);
            float e1 = __expf(s1 - m);
            float inv = __fdividef(1.f, e0 + e1);
            out[r] = make_float2(e0 * inv, e1 * inv);
        }
    }
}

extern "C" void kernel_launch(void* const* d_in, const int* in_sizes, int n_in,
                              void* d_out, int out_size) {
    const float* x  = (const float*)d_in[0];   // [256,1024,512] f32
    const float* tf = (const float*)d_in[1];   // [2,512] f32
    const float* ls = (const float*)d_in[2];   // [1] f32
    float2* out = (float2*)d_out;              // [262144,2] f32

    prompts_kernel<<<GRID, TPB>>>((const float4*)x, (const float4*)tf, ls, out);
}